// round 1
// baseline (speedup 1.0000x reference)
#include <cuda_runtime.h>
#include <math.h>
#include <float.h>

#define NB 16
#define NA 5
#define NH 96
#define NW 96
#define MAXT 50
#define NCLS 40
#define CH (5 + NCLS)          // 45
#define NCELL (NB*NA*NH*NW)    // 737280
#define PLANE (NH*NW)          // 9216

// Device scratch (no allocations allowed)
__device__ float g_mask[NCELL];
__device__ float g_cmask[NCELL];
__device__ float g_tx[NCELL];
__device__ float g_ty[NCELL];
__device__ float g_tw[NCELL];
__device__ float g_th[NCELL];
__device__ int   g_tlabel[NCELL];
// acc: 0 sx,1 sy,2 sw,3 sh,4 neg_sum,5 neg_cnt,6 pos_sum,7 nM,8 cls_sum,9 nProp,10 nGT,11 nCorrect
__device__ float g_acc[16];

__global__ void k_init() {
    int i = blockIdx.x * blockDim.x + threadIdx.x;
    if (i < NCELL) {
        g_mask[i]  = 0.0f;
        g_cmask[i] = 1.0f;
    }
    if (i < 16) g_acc[i] = 0.0f;
}

__global__ void k_build(const float* __restrict__ pred,
                        const float* __restrict__ target,
                        const int*   __restrict__ tsizes) {
    const int b = blockIdx.x;
    const int t = threadIdx.x;

    __shared__ int   s_gi[MAXT], s_gj[MAXT], s_best[MAXT], s_lbl[MAXT], s_cor[MAXT];
    __shared__ float s_tx[MAXT], s_ty[MAXT], s_tw[MAXT], s_th[MAXT];
    __shared__ unsigned s_ign[MAXT];

    int ts = tsizes[b];
    if (ts > MAXT) ts = MAXT;

    const float AW[5] = {1.f, 2.f, 4.f, 2.f, 4.f};
    const float AH[5] = {1.f, 2.f, 4.f, 4.f, 2.f};

    if (t < MAXT && t < ts) {
        const float* row = target + ((long)(b * MAXT + t)) * (13 + NCLS);
        float gx = row[0] * (1.0f / 16.0f);
        float gy = row[1] * (1.0f / 16.0f);
        float gh = row[3] * (1.0f / 16.0f);
        float gw = row[4] * (1.0f / 16.0f);
        int gi = (int)gx;
        int gj = (int)gy;

        // label = argmax over one-hot (first max)
        int lbl = 0; float bv = row[13];
        #pragma unroll
        for (int c = 1; c < NCLS; c++) {
            float v = row[13 + c];
            if (v > bv) { bv = v; lbl = c; }
        }

        // anchor IoUs
        float garea = (gw + 1.0f) * (gh + 1.0f);
        float best_iou = -1.0f; int best = 0; unsigned ign = 0u;
        #pragma unroll
        for (int a = 0; a < 5; a++) {
            float iw = fminf(gw, AW[a]) + 1.0f; iw = fmaxf(iw, 0.0f);
            float ih = fminf(gh, AH[a]) + 1.0f; ih = fmaxf(ih, 0.0f);
            float inter = iw * ih;
            float aa = (AW[a] + 1.0f) * (AH[a] + 1.0f);
            float iou = inter / (garea + aa - inter + 1e-16f);
            if (iou > 0.5f) ign |= (1u << a);
            if (iou > best_iou) { best_iou = iou; best = a; }  // first-max tie rule
        }

        s_gi[t] = gi; s_gj[t] = gj; s_best[t] = best; s_lbl[t] = lbl; s_ign[t] = ign;
        s_tx[t] = gx - (float)gi;
        s_ty[t] = gy - (float)gj;
        s_tw[t] = logf(gw / AW[best] + 1e-16f);
        s_th[t] = logf(gh / AH[best] + 1e-16f);

        // prediction at best cell (for nCorrect)
        long base = ((((long)b * NA + best) * NH + gj) * NW + gi) * CH;
        float pc = pred[base + 0];
        float x = pred[base + 1], y = pred[base + 2];
        float h = pred[base + 3], w = pred[base + 4];
        float px = x + (float)gi, py = y + (float)gj;
        float pw = expf(w) * AW[best];
        float ph = expf(h) * AH[best];

        float gx1 = gx - gw * 0.5f, gx2 = gx + gw * 0.5f;
        float gy1 = gy - gh * 0.5f, gy2 = gy + gh * 0.5f;
        float px1 = px - pw * 0.5f, px2 = px + pw * 0.5f;
        float py1 = py - ph * 0.5f, py2 = py + ph * 0.5f;
        float iw2 = fmaxf(fminf(gx2, px2) - fmaxf(gx1, px1) + 1.0f, 0.0f);
        float ih2 = fmaxf(fminf(gy2, py2) - fmaxf(gy1, py1) + 1.0f, 0.0f);
        float inter2 = iw2 * ih2;
        float ga = (gx2 - gx1 + 1.0f) * (gy2 - gy1 + 1.0f);
        float pa = (px2 - px1 + 1.0f) * (py2 - py1 + 1.0f);
        float iou2 = inter2 / (ga + pa - inter2 + 1e-16f);

        // pred class argmax (first max)
        int cb = 0; float cbv = pred[base + 5];
        #pragma unroll
        for (int c = 1; c < NCLS; c++) {
            float v = pred[base + 5 + c];
            if (v > cbv) { cbv = v; cb = c; }
        }
        s_cor[t] = (iou2 > 0.5f && cb == lbl && pc > 0.5f) ? 1 : 0;
    }
    __syncthreads();

    // Serial replay of map writes (ordering matters for collisions)
    if (t == 0) {
        int nGT = 0, nC = 0;
        for (int i = 0; i < ts; i++) {
            nGT++; nC += s_cor[i];
            int gi = s_gi[i], gj = s_gj[i], best = s_best[i];
            long col = (((long)b * NA) * NH + gj) * NW + gi;  // anchor 0
            unsigned ign = s_ign[i];
            #pragma unroll
            for (int a = 0; a < 5; a++)
                if ((ign >> a) & 1u) g_cmask[col + (long)a * PLANE] = 0.0f;
            long ib = col + (long)best * PLANE;
            g_cmask[ib] = 1.0f;
            g_mask[ib]  = 1.0f;
            g_tx[ib] = s_tx[i];
            g_ty[ib] = s_ty[i];
            g_tw[ib] = s_tw[i];
            g_th[ib] = s_th[i];
            g_tlabel[ib] = s_lbl[i];
        }
        atomicAdd(&g_acc[10], (float)nGT);
        atomicAdd(&g_acc[11], (float)nC);
    }
}

__global__ void k_sweep(const float* __restrict__ pred) {
    const int cell = blockIdx.x * blockDim.x + threadIdx.x;

    float v[10]; // sx,sy,sw,sh,neg,negc,pos,nm,scls,nprop
    #pragma unroll
    for (int k = 0; k < 10; k++) v[k] = 0.0f;

    if (cell < NCELL) {
        float m  = g_mask[cell];
        float cm = g_cmask[cell];
        const float* p = pred + (long)cell * CH;
        float pc = p[0];
        float bce = fmaxf(pc, 0.0f) - pc * m + log1pf(expf(-fabsf(pc)));
        if (cm != m) { v[4] = bce; v[5] = 1.0f; }
        v[6] = m * bce;
        v[7] = m;
        v[9] = (pc > 0.0f) ? 1.0f : 0.0f;
        if (m != 0.0f) {
            float x = p[1], y = p[2], h = p[3], w = p[4];
            float dx = x - g_tx[cell]; v[0] = dx * dx;
            float dy = y - g_ty[cell]; v[1] = dy * dy;
            float dw = w - g_tw[cell]; v[2] = dw * dw;
            float dh = h - g_th[cell]; v[3] = dh * dh;
            int lbl = g_tlabel[cell];
            float mx = -FLT_MAX;
            for (int c = 0; c < NCLS; c++) mx = fmaxf(mx, p[5 + c]);
            float s = 0.0f;
            for (int c = 0; c < NCLS; c++) s += expf(p[5 + c] - mx);
            v[8] = -(p[5 + lbl] - mx - logf(s));
        }
    }

    // block reduce 10 accumulators
    __shared__ float red[8][10];
    int lane = threadIdx.x & 31;
    int warp = threadIdx.x >> 5;
    #pragma unroll
    for (int k = 0; k < 10; k++) {
        float x = v[k];
        #pragma unroll
        for (int off = 16; off > 0; off >>= 1)
            x += __shfl_down_sync(0xFFFFFFFFu, x, off);
        if (lane == 0) red[warp][k] = x;
        v[k] = x;
    }
    __syncthreads();
    if (warp == 0) {
        #pragma unroll
        for (int k = 0; k < 10; k++) {
            float x = (lane < (blockDim.x >> 5)) ? red[lane][k] : 0.0f;
            #pragma unroll
            for (int off = 16; off > 0; off >>= 1)
                x += __shfl_down_sync(0xFFFFFFFFu, x, off);
            if (lane == 0 && x != 0.0f) atomicAdd(&g_acc[k], x);
        }
    }
}

__global__ void k_final(float* __restrict__ out) {
    if (threadIdx.x != 0 || blockIdx.x != 0) return;
    float nM = g_acc[7];
    float lx = g_acc[0] / nM;
    float ly = g_acc[1] / nM;
    float lw = g_acc[2] / nM;
    float lh = g_acc[3] / nM;
    float lcoord = lx + ly + lw + lh;
    float lconf = g_acc[4] / g_acc[5] + g_acc[6] / nM;
    float lcls = (1.0f / (float)NB) * g_acc[8] / nM;
    float loss = lx + ly + lw + lh + lconf + lcls;
    float nGT = g_acc[10], nC = g_acc[11], nP = g_acc[9];
    float recall = nC / fmaxf(nGT, 1.0f);
    float precision = (nP > 0.0f) ? (nC / fmaxf(nP, 1.0f)) : 1.0f;
    out[0] = loss;
    out[1] = lcoord;
    out[2] = lconf;
    out[3] = lcls;
    out[4] = recall;
    out[5] = precision;
}

extern "C" void kernel_launch(void* const* d_in, const int* in_sizes, int n_in,
                              void* d_out, int out_size) {
    const float* pred   = (const float*)d_in[0];
    const float* target = (const float*)d_in[1];
    const int*   tsz    = (const int*)d_in[2];
    float* out = (float*)d_out;

    (void)in_sizes; (void)n_in; (void)out_size;

    k_init<<<(NCELL + 255) / 256, 256>>>();
    k_build<<<NB, 64>>>(pred, target, tsz);
    k_sweep<<<(NCELL + 255) / 256, 256>>>(pred);
    k_final<<<1, 32>>>(out);
}